// round 4
// baseline (speedup 1.0000x reference)
#include <cuda_runtime.h>
#include <cuda_bf16.h>

// 3D ROI pooling, divide-free padded-index version.
//   img:  (1, 256, 256, 256, 8) fp32, layout ((ix*256+iy)*256+iz)*8 + c
//   rois: (1, 64, 6) int32  [x, y, z, w, h, d]
//   out:  (1, 64, 7, 7, 7, 8) fp32
//
// Index space padded to powers of two: tid = roi<<10 | px<<7 | py<<4 | pz<<1 | half.
// px,py,pz in [0,8), active when < 7. Decode is pure bit ops -> the 8
// independent LDG.128s issue with a minimal leading dependency chain.
// Lane order (half fastest, then pz) makes each LDG's warp footprint a
// contiguous z-run of a single (ix,iy) row -> fewer line-wavefronts.

#define NUM_ROIS 64
#define PS 7
#define CELLS (PS * PS * PS)            // 343
#define DIM 256

__global__ void __launch_bounds__(128) roi_pool3d_kernel(
    const float* __restrict__ img,
    const int* __restrict__ rois,
    float* __restrict__ out)
{
    int tid = blockIdx.x * 128 + threadIdx.x;   // 0 .. 65535

    int half = tid & 1;
    int pz   = (tid >> 1) & 7;
    int py   = (tid >> 4) & 7;
    int px   = (tid >> 7) & 7;
    int roi  = tid >> 10;

    if (px == 7 || py == 7 || pz == 7) return;   // padding lanes

    const int* r = rois + roi * 6;
    int x = __ldg(r + 0), y = __ldg(r + 1), z = __ldg(r + 2);
    int w = __ldg(r + 3), h = __ldg(r + 4), d = __ldg(r + 5);

    // --- axis coords (match reference fp32 arithmetic) ---
    float sx = (float)px * ((float)w * (1.0f / PS));
    // NOTE: reference computes size/ps then multiplies; keep that exact order:
    sx = (float)px * ((float)w / (float)PS);
    int ix0 = (int)floorf(sx);
    float fx = sx - (float)ix0;
    int ix1 = min(ix0 + 1, w - 1);
    ix0 = min(ix0, w - 1);

    float sy = (float)py * ((float)h / (float)PS);
    int iy0 = (int)floorf(sy);
    float fy = sy - (float)iy0;
    int iy1 = min(iy0 + 1, h - 1);
    iy0 = min(iy0, h - 1);

    float sz = (float)pz * ((float)d / (float)PS);
    int iz0 = (int)floorf(sz);
    float fz = sz - (float)iz0;
    int iz1 = min(iz0 + 1, d - 1);
    iz0 = min(iz0, d - 1);

    int jx0 = x + ix0, jx1 = x + ix1;
    int jy0 = y + iy0, jy1 = y + iy1;
    int jz0 = z + iz0, jz1 = z + iz1;

    // float4 index: ((ix*256+iy)*256+iz)*2 + half
    const float4* __restrict__ base = (const float4*)img;
    int row00 = (jx0 * DIM + jy0) * DIM;
    int row01 = (jx0 * DIM + jy1) * DIM;
    int row10 = (jx1 * DIM + jy0) * DIM;
    int row11 = (jx1 * DIM + jy1) * DIM;

    size_t b000 = (size_t)(row00 + jz0) * 2 + half;
    size_t b001 = (size_t)(row00 + jz1) * 2 + half;
    size_t b010 = (size_t)(row01 + jz0) * 2 + half;
    size_t b011 = (size_t)(row01 + jz1) * 2 + half;
    size_t b100 = (size_t)(row10 + jz0) * 2 + half;
    size_t b101 = (size_t)(row10 + jz1) * 2 + half;
    size_t b110 = (size_t)(row11 + jz0) * 2 + half;
    size_t b111 = (size_t)(row11 + jz1) * 2 + half;

    // 8 independent LDG.128 (MLP = 8)
    float4 v000 = base[b000];
    float4 v001 = base[b001];
    float4 v010 = base[b010];
    float4 v011 = base[b011];
    float4 v100 = base[b100];
    float4 v101 = base[b101];
    float4 v110 = base[b110];
    float4 v111 = base[b111];

    float gz = 1.0f - fz, gy = 1.0f - fy, gx = 1.0f - fx;

    float4 o;
    {
        float c00, c01, c10, c11, c0, c1;
        c00 = v000.x * gz + v001.x * fz;
        c01 = v010.x * gz + v011.x * fz;
        c10 = v100.x * gz + v101.x * fz;
        c11 = v110.x * gz + v111.x * fz;
        c0 = c00 * gy + c01 * fy;
        c1 = c10 * gy + c11 * fy;
        o.x = c0 * gx + c1 * fx;

        c00 = v000.y * gz + v001.y * fz;
        c01 = v010.y * gz + v011.y * fz;
        c10 = v100.y * gz + v101.y * fz;
        c11 = v110.y * gz + v111.y * fz;
        c0 = c00 * gy + c01 * fy;
        c1 = c10 * gy + c11 * fy;
        o.y = c0 * gx + c1 * fx;

        c00 = v000.z * gz + v001.z * fz;
        c01 = v010.z * gz + v011.z * fz;
        c10 = v100.z * gz + v101.z * fz;
        c11 = v110.z * gz + v111.z * fz;
        c0 = c00 * gy + c01 * fy;
        c1 = c10 * gy + c11 * fy;
        o.z = c0 * gx + c1 * fx;

        c00 = v000.w * gz + v001.w * fz;
        c01 = v010.w * gz + v011.w * fz;
        c10 = v100.w * gz + v101.w * fz;
        c11 = v110.w * gz + v111.w * fz;
        c0 = c00 * gy + c01 * fy;
        c1 = c10 * gy + c11 * fy;
        o.w = c0 * gx + c1 * fx;
    }

    // output vec index = (roi*343 + ((px*7+py)*7+pz))*2 + half
    int cell = (px * PS + py) * PS + pz;
    size_t vec = (size_t)(roi * CELLS + cell) * 2 + half;
    ((float4*)out)[vec] = o;
}

extern "C" void kernel_launch(void* const* d_in, const int* in_sizes, int n_in,
                              void* d_out, int out_size)
{
    const float* img  = (const float*)d_in[0];
    const int*   rois = (const int*)d_in[1];
    float*       out  = (float*)d_out;

    // 64 rois * 1024 padded slots = 65536 threads
    roi_pool3d_kernel<<<512, 128>>>(img, rois, out);
}